// round 12
// baseline (speedup 1.0000x reference)
#include <cuda_runtime.h>
#include <math.h>
#include <stdint.h>

#define BB 8
#define CC 128
#define HWM 4096
#define TN 64
#define NT 64
#define NTHREADS 256

// ---- smem float offsets ----
#define KN0_F 0          // Kn buf [64 n][132], 8448 f each
#define KN1_F 8448
#define VC0_F 16896      // Vc buf [128 c][68], 8704 f each
#define VC1_F 25600
#define P0_F  34304      // P buf [128 r][68], 8704 f each
#define P1_F  43008
#define RL_F  51712      // 1/l per row [128]
#define QS_F  16896      // Q staging [128][132] overlaps Vc0/Vc1
#define SMEM_FLOATS 51840   // 207360 bytes

// named barrier ids (count 256 unless noted):
//  1+buf : KVREADY  (PV arrives, S syncs)
//  3+buf : PFULL    (S arrives, PV syncs)
//  5+buf : PFREE    (PV arrives, S syncs; first used at t=2)
//  7     : PV-group internal (count 128)

__device__ float g_At[3 * CC * CC];
__device__ float g_dv[CC];
__device__ uint32_t g_curT[BB * HWM * CC];  // [b][n][c] RNA tf32
__device__ uint32_t g_curC[BB * CC * HWM];  // [b][c][n] RNA tf32

__global__ void prep_kernel(const float* __restrict__ w1, const float* __restrict__ b1,
                            const float* __restrict__ gamma, const float* __restrict__ beta,
                            const float* __restrict__ rmean, const float* __restrict__ rvar)
{
    int i = blockIdx.x * blockDim.x + threadIdx.x;
    if (i < 3 * CC * CC) {
        int c = i / CC;
        int o = i % CC;
        float inv = gamma[o] * rsqrtf(rvar[o] + 1e-5f);
        g_At[c * CC + o] = w1[o * (3 * CC) + c] * inv;
    }
    if (i < CC) {
        float inv = gamma[i] * rsqrtf(rvar[i] + 1e-5f);
        g_dv[i] = b1[i] * inv + beta[i] - rmean[i] * inv;
    }
}

__device__ __forceinline__ uint32_t d_f2tf32(float f) {
    uint32_t r;
    asm("cvt.rna.tf32.f32 %0, %1;" : "=r"(r) : "f"(f));
    return r;
}

__global__ void conv_kernel(const float* __restrict__ cur)
{
    int i = blockIdx.x * blockDim.x + threadIdx.x;
    float4 v = ((const float4*)cur)[i];
    uint4 t = make_uint4(d_f2tf32(v.x), d_f2tf32(v.y), d_f2tf32(v.z), d_f2tf32(v.w));
    ((uint4*)g_curC)[i] = t;
}

__global__ void transpose_kernel(const float* __restrict__ cur)
{
    __shared__ uint32_t t[32][33];
    int b  = blockIdx.z;
    int n0 = blockIdx.x * 32;
    int c0 = blockIdx.y * 32;
    const float* src = cur + ((size_t)b * CC + c0) * HWM + n0;
    #pragma unroll
    for (int i = 0; i < 4; i++)
        t[threadIdx.y + i * 8][threadIdx.x] =
            d_f2tf32(src[(threadIdx.y + i * 8) * HWM + threadIdx.x]);
    __syncthreads();
    uint32_t* dst = g_curT + ((size_t)b * HWM + n0) * CC + c0;
    #pragma unroll
    for (int i = 0; i < 4; i++)
        dst[(threadIdx.y + i * 8) * CC + threadIdx.x] = t[threadIdx.x][threadIdx.y + i * 8];
}

// ---------- helpers ----------
__device__ __forceinline__ uint32_t smem_u32(const void* p) {
    return (uint32_t)__cvta_generic_to_shared(p);
}
__device__ __forceinline__ void ldsm4(uint32_t& r0, uint32_t& r1, uint32_t& r2, uint32_t& r3,
                                      uint32_t addr) {
    asm volatile("ldmatrix.sync.aligned.m8n8.x4.shared.b16 {%0,%1,%2,%3}, [%4];"
                 : "=r"(r0), "=r"(r1), "=r"(r2), "=r"(r3) : "r"(addr));
}
__device__ __forceinline__ void mma_tf32(float& d0, float& d1, float& d2, float& d3,
                                         uint32_t a0, uint32_t a1, uint32_t a2, uint32_t a3,
                                         uint32_t b0, uint32_t b1) {
    asm volatile("mma.sync.aligned.m16n8k8.row.col.f32.tf32.tf32.f32 "
                 "{%0,%1,%2,%3}, {%4,%5,%6,%7}, {%8,%9}, {%0,%1,%2,%3};"
                 : "+f"(d0), "+f"(d1), "+f"(d2), "+f"(d3)
                 : "r"(a0), "r"(a1), "r"(a2), "r"(a3), "r"(b0), "r"(b1));
}
__device__ __forceinline__ float ex2f(float x) {
    float r; asm("ex2.approx.f32 %0, %1;" : "=f"(r) : "f"(x)); return r;
}
__device__ __forceinline__ void cp16(uint32_t saddr, const void* gaddr) {
    asm volatile("cp.async.cg.shared.global [%0], [%1], 16;" :: "r"(saddr), "l"(gaddr));
}
#define CP_COMMIT() asm volatile("cp.async.commit_group;" ::: "memory")
#define CP_WAIT1()  asm volatile("cp.async.wait_group 1;"  ::: "memory")
#define CP_WAIT0()  asm volatile("cp.async.wait_group 0;"  ::: "memory")
__device__ __forceinline__ void barx_sync(int id, int cnt) {
    asm volatile("bar.sync %0, %1;" :: "r"(id), "r"(cnt) : "memory");
}
__device__ __forceinline__ void barx_arrive(int id, int cnt) {
    asm volatile("bar.arrive %0, %1;" :: "r"(id), "r"(cnt) : "memory");
}

// Prefetch one K/V tile with 128 threads (PV group). 32 cp16/thread.
__device__ __forceinline__ void prefetch_tile2(uint32_t knb, uint32_t vcb,
                                               const uint32_t* __restrict__ curCb,
                                               const uint32_t* __restrict__ curTb,
                                               int n0, int tid2)
{
    #pragma unroll
    for (int rep = 0; rep < 16; rep++) {                 // Vc [128 c][64 n]
        int idx = rep * 128 + tid2;
        int c = idx >> 4, q = idx & 15;
        cp16(vcb + (c * 68 + q * 4) * 4, curCb + (size_t)c * HWM + n0 + q * 4);
    }
    #pragma unroll
    for (int rep = 0; rep < 16; rep++) {                 // Kn [64 n][128 c]
        int idx = rep * 128 + tid2;
        int n = idx >> 5, q = idx & 31;
        cp16(knb + (n * 132 + q * 4) * 4, curTb + (size_t)(n0 + n) * CC + q * 4);
    }
    CP_COMMIT();
}

// ---------------------------------------------------------------------------
// Warp-specialized fused dual-attention (tf32 mma.sync) + folded cls head.
// Grid (64, 8), 256 threads. Warps 0-3: S-group — each owns 32 of 128 logical
// Q rows (Q A-frags register-resident), computes S = Q K^T, softmax p = 2^s
// (log2e folded in Q scale; logits bounded -> no max, no rescale), writes P.
// Warps 4-7: PV-group — warp p: rows 64*(p>>1), channels 64*(p&1); O += P V;
// also issues all cp.async tile loads. P double-buffered; named-barrier
// producer/consumer pipeline so softmax (MUFU) overlaps PV HMMAs per SMSP.
// ---------------------------------------------------------------------------
__global__ void __launch_bounds__(NTHREADS, 1)
fused_attn_ws(const float* __restrict__ reff, const float* __restrict__ curf,
              const float* __restrict__ w2, const float* __restrict__ b2,
              float* __restrict__ out)
{
    extern __shared__ float sm[];

    const int b    = blockIdx.y;
    const int m0   = blockIdx.x * 64;
    const int tid  = threadIdx.x;
    const int warp = tid >> 5;
    const int lane = tid & 31;
    const int g    = lane >> 3;
    const int rr   = lane & 7;

    const float* __restrict__ curb     = curf + (size_t)b * CC * HWM;
    const float* __restrict__ refb     = reff + (size_t)b * CC * HWM;
    const uint32_t* __restrict__ curTb = g_curT + (size_t)b * HWM * CC;
    const uint32_t* __restrict__ curCb = g_curC + (size_t)b * CC * HWM;

    const float QSC = 0.12751744154f;   // (1/sqrt(128)) * log2(e)

    // ---- Stage Q (scaled, RNA tf32) into Qs [128 r][132] (all threads) ----
    {
        float* Qs = sm + QS_F;
        #pragma unroll
        for (int rep = 0; rep < 8; rep++) {
            int c  = rep * 16 + (tid >> 4);
            int m4 = (tid & 15) * 4;
            float4 vr = *(const float4*)(refb + (size_t)c * HWM + m0 + m4);
            float4 vc = *(const float4*)(curb + (size_t)c * HWM + m0 + m4);
            Qs[(m4 + 0) * 132 + c] = __uint_as_float(d_f2tf32(vr.x * QSC));
            Qs[(m4 + 1) * 132 + c] = __uint_as_float(d_f2tf32(vr.y * QSC));
            Qs[(m4 + 2) * 132 + c] = __uint_as_float(d_f2tf32(vr.z * QSC));
            Qs[(m4 + 3) * 132 + c] = __uint_as_float(d_f2tf32(vr.w * QSC));
            Qs[(64 + m4 + 0) * 132 + c] = __uint_as_float(d_f2tf32(vc.x * QSC));
            Qs[(64 + m4 + 1) * 132 + c] = __uint_as_float(d_f2tf32(vc.y * QSC));
            Qs[(64 + m4 + 2) * 132 + c] = __uint_as_float(d_f2tf32(vc.z * QSC));
            Qs[(64 + m4 + 3) * 132 + c] = __uint_as_float(d_f2tf32(vc.w * QSC));
        }
    }
    __syncthreads();

    float lp[2][2];
    lp[0][0] = 0.f; lp[0][1] = 0.f; lp[1][0] = 0.f; lp[1][1] = 0.f;
    float O[4][8][4];

    if (warp < 4) {
        // =================== S / softmax group ===================
        uint32_t Qr[2][16][4];
        #pragma unroll
        for (int mb2 = 0; mb2 < 2; mb2++) {
            uint32_t qbase = smem_u32(sm + QS_F +
                (32 * warp + 16 * mb2 + (g & 1) * 8 + rr) * 132 + (g >> 1) * 4);
            #pragma unroll
            for (int kb = 0; kb < 16; kb++)
                ldsm4(Qr[mb2][kb][0], Qr[mb2][kb][1], Qr[mb2][kb][2], Qr[mb2][kb][3],
                      qbase + kb * 8 * 4);
        }
        __syncthreads();   // Q staging free (PV group waits here too)

        const uint32_t kn_off = (rr * 132 + g * 4) * 4;
        const int rbase = 32 * warp + (lane >> 2);
        const int col   = 2 * (lane & 3);

        for (int t = 0; t < NT; t++) {
            const int buf = t & 1;
            barx_sync(1 + buf, 256);                 // KV tile t ready
            if (t >= 2) barx_sync(5 + buf, 256);     // P[buf] free (PV(t-2) done)

            const uint32_t knb = smem_u32(sm + (buf ? KN1_F : KN0_F)) + kn_off;
            float* Pp = sm + (buf ? P1_F : P0_F);

            #pragma unroll
            for (int nh = 0; nh < 2; nh++) {
                float s[2][4][4];
                #pragma unroll
                for (int mb2 = 0; mb2 < 2; mb2++)
                    #pragma unroll
                    for (int nb = 0; nb < 4; nb++) {
                        s[mb2][nb][0] = 0.f; s[mb2][nb][1] = 0.f;
                        s[mb2][nb][2] = 0.f; s[mb2][nb][3] = 0.f;
                    }
                #pragma unroll
                for (int kb2 = 0; kb2 < 8; kb2++) {
                    #pragma unroll
                    for (int nb = 0; nb < 4; nb++) {
                        int nbg = nh * 4 + nb;
                        uint32_t b0, b1, b2_, b3_;
                        ldsm4(b0, b1, b2_, b3_, knb + (nbg * 8 * 132 + kb2 * 16) * 4);
                        #pragma unroll
                        for (int mb2 = 0; mb2 < 2; mb2++) {
                            mma_tf32(s[mb2][nb][0], s[mb2][nb][1], s[mb2][nb][2], s[mb2][nb][3],
                                     Qr[mb2][2 * kb2][0], Qr[mb2][2 * kb2][1],
                                     Qr[mb2][2 * kb2][2], Qr[mb2][2 * kb2][3], b0, b1);
                            mma_tf32(s[mb2][nb][0], s[mb2][nb][1], s[mb2][nb][2], s[mb2][nb][3],
                                     Qr[mb2][2 * kb2 + 1][0], Qr[mb2][2 * kb2 + 1][1],
                                     Qr[mb2][2 * kb2 + 1][2], Qr[mb2][2 * kb2 + 1][3], b2_, b3_);
                        }
                    }
                }
                // softmax half: p = 2^s, accumulate l, store P (RNA tf32)
                #pragma unroll
                for (int mb2 = 0; mb2 < 2; mb2++) {
                    int rowA = rbase + 16 * mb2;
                    #pragma unroll
                    for (int nb = 0; nb < 4; nb++) {
                        float p0 = ex2f(s[mb2][nb][0]);
                        float p1 = ex2f(s[mb2][nb][1]);
                        float p2 = ex2f(s[mb2][nb][2]);
                        float p3 = ex2f(s[mb2][nb][3]);
                        lp[mb2][0] += p0 + p1;
                        lp[mb2][1] += p2 + p3;
                        *(uint2*)(Pp + rowA * 68 + (nh * 4 + nb) * 8 + col) =
                            make_uint2(d_f2tf32(p0), d_f2tf32(p1));
                        *(uint2*)(Pp + (rowA + 8) * 68 + (nh * 4 + nb) * 8 + col) =
                            make_uint2(d_f2tf32(p2), d_f2tf32(p3));
                    }
                }
            }
            __threadfence_block();
            barx_arrive(3 + buf, 256);               // P[buf] full
        }

        // 1/l per row
        lp[0][0] += __shfl_xor_sync(0xffffffffu, lp[0][0], 1);
        lp[0][0] += __shfl_xor_sync(0xffffffffu, lp[0][0], 2);
        lp[0][1] += __shfl_xor_sync(0xffffffffu, lp[0][1], 1);
        lp[0][1] += __shfl_xor_sync(0xffffffffu, lp[0][1], 2);
        lp[1][0] += __shfl_xor_sync(0xffffffffu, lp[1][0], 1);
        lp[1][0] += __shfl_xor_sync(0xffffffffu, lp[1][0], 2);
        lp[1][1] += __shfl_xor_sync(0xffffffffu, lp[1][1], 1);
        lp[1][1] += __shfl_xor_sync(0xffffffffu, lp[1][1], 2);
        if ((lane & 3) == 0) {
            #pragma unroll
            for (int mb2 = 0; mb2 < 2; mb2++) {
                int rowA = 32 * warp + 16 * mb2 + (lane >> 2);
                sm[RL_F + rowA]     = 1.0f / lp[mb2][0];
                sm[RL_F + rowA + 8] = 1.0f / lp[mb2][1];
            }
        }
    } else {
        // =================== PV / loader group ===================
        __syncthreads();   // matches S-group's post-Qr barrier; QS now free

        const int tid2 = tid - 128;
        const int p  = warp - 4;
        const int pr = p >> 1;          // row half
        const int pc = p & 1;           // channel half

        #pragma unroll
        for (int mb = 0; mb < 4; mb++)
            #pragma unroll
            for (int cb = 0; cb < 8; cb++) {
                O[mb][cb][0] = 0.f; O[mb][cb][1] = 0.f;
                O[mb][cb][2] = 0.f; O[mb][cb][3] = 0.f;
            }

        const uint32_t kn_s[2] = { smem_u32(sm + KN0_F), smem_u32(sm + KN1_F) };
        const uint32_t vc_s[2] = { smem_u32(sm + VC0_F), smem_u32(sm + VC1_F) };
        const uint32_t pp_s[2] = { smem_u32(sm + P0_F),  smem_u32(sm + P1_F)  };
        const uint32_t pp_off = ((64 * pr + (g & 1) * 8 + rr) * 68 + (g >> 1) * 4) * 4;
        const uint32_t vc_off = ((64 * pc + (g >> 1) * 8 + rr) * 68 + (g & 1) * 4) * 4;

        prefetch_tile2(kn_s[0], vc_s[0], curCb, curTb, 0, tid2);   // tile 0

        for (int t = 0; t < NT; t++) {
            const int buf = t & 1;
            if (t + 1 < NT) {
                prefetch_tile2(kn_s[buf ^ 1], vc_s[buf ^ 1], curCb, curTb,
                               (t + 1) * TN, tid2);
                CP_WAIT1();          // tile t resident; t+1 in flight
            } else {
                CP_WAIT0();
            }
            __threadfence_block();
            barx_arrive(1 + buf, 256);               // KV tile t ready
            barx_sync(3 + buf, 256);                 // wait P[buf] full

            const uint32_t ppb = pp_s[buf] + pp_off;
            const uint32_t vcb = vc_s[buf] + vc_off;
            #pragma unroll
            for (int jb = 0; jb < 8; jb++) {
                uint32_t a[4][4];
                #pragma unroll
                for (int mb = 0; mb < 4; mb++)
                    ldsm4(a[mb][0], a[mb][1], a[mb][2], a[mb][3],
                          ppb + (16 * mb * 68 + jb * 8) * 4);
                #pragma unroll
                for (int cb2 = 0; cb2 < 4; cb2++) {
                    uint32_t b0, b1, b2_, b3_;
                    ldsm4(b0, b1, b2_, b3_, vcb + (cb2 * 16 * 68 + jb * 8) * 4);
                    #pragma unroll
                    for (int mb = 0; mb < 4; mb++) {
                        mma_tf32(O[mb][2 * cb2][0], O[mb][2 * cb2][1],
                                 O[mb][2 * cb2][2], O[mb][2 * cb2][3],
                                 a[mb][0], a[mb][1], a[mb][2], a[mb][3], b0, b1);
                        mma_tf32(O[mb][2 * cb2 + 1][0], O[mb][2 * cb2 + 1][1],
                                 O[mb][2 * cb2 + 1][2], O[mb][2 * cb2 + 1][3],
                                 a[mb][0], a[mb][1], a[mb][2], a[mb][3], b2_, b3_);
                    }
                }
            }
            barx_arrive(5 + buf, 256);               // P[buf] free
            barx_sync(7, 128);                       // PV-group: tile t fully read
        }
    }
    __syncthreads();   // join groups; RL written; all smem free

    // ---- Build X = [feats0; feats1; cur] : Xs[384][68] over 64 m ----
    float* Xs = sm;
    if (warp >= 4) {
        const int p  = warp - 4;
        const int pr = p >> 1;
        const int pc = p & 1;
        #pragma unroll
        for (int mb = 0; mb < 4; mb++) {
            int rA = 64 * pr + 16 * mb + (lane >> 2);
            int rB = rA + 8;
            float rlA = sm[RL_F + rA];
            float rlB = sm[RL_F + rB];
            int aSelA = rA >> 6, mmA = rA & 63;
            int aSelB = rB >> 6, mmB = rB & 63;
            #pragma unroll
            for (int cb = 0; cb < 8; cb++) {
                int c = 64 * pc + cb * 8 + 2 * (lane & 3);
                Xs[(aSelA * CC + c    ) * 68 + mmA] = O[mb][cb][0] * rlA;
                Xs[(aSelA * CC + c + 1) * 68 + mmA] = O[mb][cb][1] * rlA;
                Xs[(aSelB * CC + c    ) * 68 + mmB] = O[mb][cb][2] * rlB;
                Xs[(aSelB * CC + c + 1) * 68 + mmB] = O[mb][cb][3] * rlB;
            }
        }
    }
    for (int i = tid; i < CC * 64; i += NTHREADS) {
        int c  = i >> 6;
        int mm = i & 63;
        Xs[(2 * CC + c) * 68 + mm] = curb[(size_t)c * HWM + m0 + mm];
    }
    __syncthreads();

    // ---- cls head: y[o][m] = sum_c At[c][o] X[c][m] + dv[o]; leaky; *w2[o] ----
    float y[32];
    float w2o;
    {
        int o    = tid & 127;
        int half = tid >> 7;
        float dv = g_dv[o];
        #pragma unroll
        for (int q = 0; q < 32; q++) y[q] = dv;

        const float* xb = Xs + half * 32;
        #pragma unroll 2
        for (int c = 0; c < 3 * CC; c++) {
            float a = g_At[c * CC + o];
            const float4* xp = (const float4*)(xb + c * 68);
            #pragma unroll
            for (int v = 0; v < 8; v++) {
                float4 x = xp[v];
                y[4 * v + 0] += a * x.x;
                y[4 * v + 1] += a * x.y;
                y[4 * v + 2] += a * x.z;
                y[4 * v + 3] += a * x.w;
            }
        }
        w2o = w2[o];
    }
    __syncthreads();

    float* Ys = sm;    // [128][66]
    {
        int o    = tid & 127;
        int half = tid >> 7;
        #pragma unroll
        for (int q = 0; q < 32; q++) {
            float v = y[q];
            v = (v > 0.0f) ? v : 0.01f * v;
            Ys[o * 66 + half * 32 + q] = w2o * v;
        }
    }
    __syncthreads();

    if (tid < 64) {
        float ssum = b2[0];
        #pragma unroll 4
        for (int o = 0; o < CC; o++) ssum += Ys[o * 66 + tid];
        out[(size_t)b * HWM + m0 + tid] = ssum;
    }
}

extern "C" void kernel_launch(void* const* d_in, const int* in_sizes, int n_in,
                              void* d_out, int out_size)
{
    const float* ref_feat = (const float*)d_in[0];
    const float* cur_feat = (const float*)d_in[1];
    const float* w1       = (const float*)d_in[2];
    const float* b1       = (const float*)d_in[3];
    const float* gamma    = (const float*)d_in[4];
    const float* beta     = (const float*)d_in[5];
    const float* rmean    = (const float*)d_in[6];
    const float* rvar     = (const float*)d_in[7];
    const float* w2       = (const float*)d_in[8];
    const float* b2       = (const float*)d_in[9];
    float* out            = (float*)d_out;

    prep_kernel<<<(3 * CC * CC + 255) / 256, 256>>>(w1, b1, gamma, beta, rmean, rvar);
    conv_kernel<<<(BB * CC * HWM / 4) / 256, 256>>>(cur_feat);
    dim3 tgrid(HWM / 32, CC / 32, BB);
    transpose_kernel<<<tgrid, dim3(32, 8)>>>(cur_feat);

    const int smem_bytes = SMEM_FLOATS * 4;  // 207360
    cudaFuncSetAttribute(fused_attn_ws,
                         cudaFuncAttributeMaxDynamicSharedMemorySize, smem_bytes);

    dim3 grid(HWM / 64, BB);
    fused_attn_ws<<<grid, NTHREADS, smem_bytes>>>(ref_feat, cur_feat, w2, b2, out);
}

// round 13
// speedup vs baseline: 1.0208x; 1.0208x over previous
#include <cuda_runtime.h>
#include <math.h>
#include <stdint.h>

#define BB 8
#define CC 128
#define HWM 4096
#define TN 64
#define NT 64
#define NTHREADS 256

// ---- smem float offsets ----
#define KN0_F 0          // Kn buf0 [64 n][132]  (8448 f)
#define KN1_F 8448       // Kn buf1
#define VC0_F 16896      // Vc buf0 [128 c][68]  (8704 f)
#define VC1_F 25600      // Vc buf1
#define QS_F  16896      // Q staging [128][132] overlaps Vc0+Vc1
#define SMEM_FLOATS 34304   // 137216 bytes

// Folded classifier-head weights (BN folded into w1).
__device__ float g_At[3 * CC * CC];
__device__ float g_dv[CC];
// RNA-tf32 copies of cur for cp.async tiles:
__device__ uint32_t g_curT[BB * HWM * CC];  // [b][n][c] (c contiguous) -> Kn
__device__ uint32_t g_curC[BB * CC * HWM];  // [b][c][n] (n contiguous) -> Vc

__global__ void prep_kernel(const float* __restrict__ w1, const float* __restrict__ b1,
                            const float* __restrict__ gamma, const float* __restrict__ beta,
                            const float* __restrict__ rmean, const float* __restrict__ rvar)
{
    int i = blockIdx.x * blockDim.x + threadIdx.x;
    if (i < 3 * CC * CC) {
        int c = i / CC;
        int o = i % CC;
        float inv = gamma[o] * rsqrtf(rvar[o] + 1e-5f);
        g_At[c * CC + o] = w1[o * (3 * CC) + c] * inv;
    }
    if (i < CC) {
        float inv = gamma[i] * rsqrtf(rvar[i] + 1e-5f);
        g_dv[i] = b1[i] * inv + beta[i] - rmean[i] * inv;
    }
}

__device__ __forceinline__ uint32_t d_f2tf32(float f) {
    uint32_t r;
    asm("cvt.rna.tf32.f32 %0, %1;" : "=r"(r) : "f"(f));
    return r;
}

// g_curC[i] = RNA-tf32(cur[i]); vectorized.
__global__ void conv_kernel(const float* __restrict__ cur)
{
    int i = blockIdx.x * blockDim.x + threadIdx.x;   // i indexes float4
    float4 v = ((const float4*)cur)[i];
    uint4 t = make_uint4(d_f2tf32(v.x), d_f2tf32(v.y), d_f2tf32(v.z), d_f2tf32(v.w));
    ((uint4*)g_curC)[i] = t;
}

// g_curT[b][n][c] = RNA-tf32(cur[b][c][n]). Grid (128, 4, 8), block (32, 8).
__global__ void transpose_kernel(const float* __restrict__ cur)
{
    __shared__ uint32_t t[32][33];
    int b  = blockIdx.z;
    int n0 = blockIdx.x * 32;
    int c0 = blockIdx.y * 32;
    const float* src = cur + ((size_t)b * CC + c0) * HWM + n0;
    #pragma unroll
    for (int i = 0; i < 4; i++)
        t[threadIdx.y + i * 8][threadIdx.x] =
            d_f2tf32(src[(threadIdx.y + i * 8) * HWM + threadIdx.x]);
    __syncthreads();
    uint32_t* dst = g_curT + ((size_t)b * HWM + n0) * CC + c0;
    #pragma unroll
    for (int i = 0; i < 4; i++)
        dst[(threadIdx.y + i * 8) * CC + threadIdx.x] = t[threadIdx.x][threadIdx.y + i * 8];
}

// ---------- helpers ----------
__device__ __forceinline__ uint32_t smem_u32(const void* p) {
    return (uint32_t)__cvta_generic_to_shared(p);
}
__device__ __forceinline__ void ldsm4(uint32_t& r0, uint32_t& r1, uint32_t& r2, uint32_t& r3,
                                      uint32_t addr) {
    asm volatile("ldmatrix.sync.aligned.m8n8.x4.shared.b16 {%0,%1,%2,%3}, [%4];"
                 : "=r"(r0), "=r"(r1), "=r"(r2), "=r"(r3) : "r"(addr));
}
__device__ __forceinline__ void mma_tf32(float& d0, float& d1, float& d2, float& d3,
                                         uint32_t a0, uint32_t a1, uint32_t a2, uint32_t a3,
                                         uint32_t b0, uint32_t b1) {
    asm volatile("mma.sync.aligned.m16n8k8.row.col.f32.tf32.tf32.f32 "
                 "{%0,%1,%2,%3}, {%4,%5,%6,%7}, {%8,%9}, {%0,%1,%2,%3};"
                 : "+f"(d0), "+f"(d1), "+f"(d2), "+f"(d3)
                 : "r"(a0), "r"(a1), "r"(a2), "r"(a3), "r"(b0), "r"(b1));
}
__device__ __forceinline__ float ex2f(float x) {
    float r; asm("ex2.approx.f32 %0, %1;" : "=f"(r) : "f"(x)); return r;
}
__device__ __forceinline__ void cp16(uint32_t saddr, const void* gaddr) {
    asm volatile("cp.async.cg.shared.global [%0], [%1], 16;" :: "r"(saddr), "l"(gaddr));
}
#define CP_COMMIT() asm volatile("cp.async.commit_group;" ::: "memory")
#define CP_WAIT0()  asm volatile("cp.async.wait_group 0;"  ::: "memory")

// Prefetch one K/V tile (pre-converted RNA tf32 bits). 256 threads.
__device__ __forceinline__ void prefetch_tile(uint32_t knb, uint32_t vcb,
                                              const uint32_t* __restrict__ curCb,
                                              const uint32_t* __restrict__ curTb,
                                              int n0, int tid)
{
    #pragma unroll
    for (int rep = 0; rep < 8; rep++) {                 // Vc [128 c][64 n]
        int idx = rep * 256 + tid;
        int c = idx >> 4, q = idx & 15;
        cp16(vcb + (c * 68 + q * 4) * 4, curCb + (size_t)c * HWM + n0 + q * 4);
    }
    #pragma unroll
    for (int rep = 0; rep < 8; rep++) {                 // Kn [64 n][128 c]
        int idx = rep * 256 + tid;
        int n = idx >> 5, q = idx & 31;
        cp16(knb + (n * 132 + q * 4) * 4, curTb + (size_t)(n0 + n) * CC + q * 4);
    }
    CP_COMMIT();
}

// ---------------------------------------------------------------------------
// Fused dual-attention (tf32 mma.sync, cp.async pipeline, fixed-max softmax,
// register-resident P via shfl fragment-permute) + folded cls head.
// Grid (64, 8), 256 threads = 8 warps. Warp w owns 16 of 128 logical Q rows
// (0-63 ref / 64-127 cur) for BOTH S and PV (PV over all 128 channels).
// p = 2^s (log2e folded into Q scale; logits bounded -> no max, no rescale).
// After softmax, the S C-fragment is permuted to the PV A-fragment with
// 8 shfl + 4 selects per 16x8 block: P never touches smem, so the loop has
// exactly ONE CTA barrier per tile (KV buffer handoff).
// ---------------------------------------------------------------------------
__global__ void __launch_bounds__(NTHREADS, 1)
fused_attn_rp(const float* __restrict__ reff, const float* __restrict__ curf,
              const float* __restrict__ w2, const float* __restrict__ b2,
              float* __restrict__ out)
{
    extern __shared__ float sm[];

    const int b    = blockIdx.y;
    const int m0   = blockIdx.x * 64;
    const int tid  = threadIdx.x;
    const int warp = tid >> 5;
    const int lane = tid & 31;

    const float* __restrict__ curb     = curf + (size_t)b * CC * HWM;
    const float* __restrict__ refb     = reff + (size_t)b * CC * HWM;
    const uint32_t* __restrict__ curTb = g_curT + (size_t)b * HWM * CC;
    const uint32_t* __restrict__ curCb = g_curC + (size_t)b * CC * HWM;

    const float QSC = 0.12751744154f;   // (1/sqrt(128)) * log2(e)

    // ---- Stage Q (scaled, RNA tf32) into Qs [128 r][132] ----
    {
        float* Qs = sm + QS_F;
        #pragma unroll
        for (int rep = 0; rep < 8; rep++) {
            int c  = rep * 16 + (tid >> 4);
            int m4 = (tid & 15) * 4;
            float4 vr = *(const float4*)(refb + (size_t)c * HWM + m0 + m4);
            float4 vc = *(const float4*)(curb + (size_t)c * HWM + m0 + m4);
            Qs[(m4 + 0) * 132 + c] = __uint_as_float(d_f2tf32(vr.x * QSC));
            Qs[(m4 + 1) * 132 + c] = __uint_as_float(d_f2tf32(vr.y * QSC));
            Qs[(m4 + 2) * 132 + c] = __uint_as_float(d_f2tf32(vr.z * QSC));
            Qs[(m4 + 3) * 132 + c] = __uint_as_float(d_f2tf32(vr.w * QSC));
            Qs[(64 + m4 + 0) * 132 + c] = __uint_as_float(d_f2tf32(vc.x * QSC));
            Qs[(64 + m4 + 1) * 132 + c] = __uint_as_float(d_f2tf32(vc.y * QSC));
            Qs[(64 + m4 + 2) * 132 + c] = __uint_as_float(d_f2tf32(vc.z * QSC));
            Qs[(64 + m4 + 3) * 132 + c] = __uint_as_float(d_f2tf32(vc.w * QSC));
        }
    }
    __syncthreads();

    // ---- Q A-fragments (16 kblocks x 4 regs), register-resident ----
    const int g  = lane >> 3;
    const int rr = lane & 7;
    uint32_t Qr[16][4];
    {
        uint32_t qbase = smem_u32(sm + QS_F + (16 * warp + (g & 1) * 8 + rr) * 132 + (g >> 1) * 4);
        #pragma unroll
        for (int kb = 0; kb < 16; kb++)
            ldsm4(Qr[kb][0], Qr[kb][1], Qr[kb][2], Qr[kb][3], qbase + kb * 8 * 4);
    }
    __syncthreads();   // Q frag reads done before tile0's Vc overwrites staging

    // per-thread smem bases
    const uint32_t kn_s0 = smem_u32(sm + KN0_F);
    const uint32_t kn_s1 = smem_u32(sm + KN1_F);
    const uint32_t vc_s0 = smem_u32(sm + VC0_F);
    const uint32_t vc_s1 = smem_u32(sm + VC1_F);
    const uint32_t kn_off = (rr * 132 + g * 4) * 4;
    const uint32_t vc_off = (((g >> 1) * 8 + rr) * 68 + (g & 1) * 4) * 4;

    // shuffle-permute constants (intra-quad)
    const int q     = lane & 3;
    const int src0  = (lane & ~3) | (q >> 1);
    const int src1  = src0 + 2;
    const bool qodd = (q & 1) != 0;

    float O[16][4];
    #pragma unroll
    for (int cb = 0; cb < 16; cb++) {
        O[cb][0] = 0.f; O[cb][1] = 0.f; O[cb][2] = 0.f; O[cb][3] = 0.f;
    }
    float lpA = 0.f, lpB = 0.f;

    prefetch_tile(kn_s0, vc_s0, curCb, curTb, 0, tid);   // tile 0 -> buf0

    for (int nt = 0; nt < NT; nt++) {
        const int buf = nt & 1;
        CP_WAIT0();
        __syncthreads();     // tile nt visible CTA-wide; buf^1 fully consumed

        if (nt + 1 < NT)
            prefetch_tile(buf ? kn_s0 : kn_s1, buf ? vc_s0 : vc_s1,
                          curCb, curTb, (nt + 1) * TN, tid);

        const uint32_t knb = (buf ? kn_s1 : kn_s0) + kn_off;
        const uint32_t vcb = (buf ? vc_s1 : vc_s0) + vc_off;

        // ---- S = Q K^T : 16x64 per warp ----
        float s[8][4];
        #pragma unroll
        for (int nb = 0; nb < 8; nb++) { s[nb][0] = 0.f; s[nb][1] = 0.f; s[nb][2] = 0.f; s[nb][3] = 0.f; }
        #pragma unroll
        for (int kb2 = 0; kb2 < 8; kb2++) {
            #pragma unroll
            for (int nb = 0; nb < 8; nb++) {
                uint32_t b0, b1, b2_, b3_;
                ldsm4(b0, b1, b2_, b3_, knb + (nb * 8 * 132 + kb2 * 16) * 4);
                mma_tf32(s[nb][0], s[nb][1], s[nb][2], s[nb][3],
                         Qr[2 * kb2][0], Qr[2 * kb2][1], Qr[2 * kb2][2], Qr[2 * kb2][3],
                         b0, b1);
                mma_tf32(s[nb][0], s[nb][1], s[nb][2], s[nb][3],
                         Qr[2 * kb2 + 1][0], Qr[2 * kb2 + 1][1], Qr[2 * kb2 + 1][2], Qr[2 * kb2 + 1][3],
                         b2_, b3_);
            }
        }

        // ---- per n-block: softmax (p = 2^s), permute C-frag -> A-frag, PV ----
        #pragma unroll
        for (int nb = 0; nb < 8; nb++) {
            float p0 = ex2f(s[nb][0]);
            float p1 = ex2f(s[nb][1]);
            float p2 = ex2f(s[nb][2]);
            float p3 = ex2f(s[nb][3]);
            lpA += p0 + p1;
            lpB += p2 + p3;
            uint32_t u0 = d_f2tf32(p0);
            uint32_t u1 = d_f2tf32(p1);
            uint32_t u2 = d_f2tf32(p2);
            uint32_t u3 = d_f2tf32(p3);

            // C layout: u0=(g,2q) u1=(g,2q+1) u2=(g+8,2q) u3=(g+8,2q+1)
            // A layout needed: a0=(g,q) a1=(g+8,q) a2=(g,q+4) a3=(g+8,q+4)
            uint32_t v00 = __shfl_sync(0xffffffffu, u0, src0);
            uint32_t v01 = __shfl_sync(0xffffffffu, u1, src0);
            uint32_t v20 = __shfl_sync(0xffffffffu, u2, src0);
            uint32_t v21 = __shfl_sync(0xffffffffu, u3, src0);
            uint32_t w00 = __shfl_sync(0xffffffffu, u0, src1);
            uint32_t w01 = __shfl_sync(0xffffffffu, u1, src1);
            uint32_t w20 = __shfl_sync(0xffffffffu, u2, src1);
            uint32_t w21 = __shfl_sync(0xffffffffu, u3, src1);
            uint32_t a0 = qodd ? v01 : v00;
            uint32_t a1 = qodd ? v21 : v20;
            uint32_t a2 = qodd ? w01 : w00;
            uint32_t a3 = qodd ? w21 : w20;

            // O += P(:,nb block) * V(nb block, :)
            #pragma unroll
            for (int cb2 = 0; cb2 < 8; cb2++) {
                uint32_t b0, b1, b2_, b3_;
                ldsm4(b0, b1, b2_, b3_, vcb + (cb2 * 16 * 68 + nb * 8) * 4);
                mma_tf32(O[2 * cb2][0], O[2 * cb2][1], O[2 * cb2][2], O[2 * cb2][3],
                         a0, a1, a2, a3, b0, b1);
                mma_tf32(O[2 * cb2 + 1][0], O[2 * cb2 + 1][1], O[2 * cb2 + 1][2], O[2 * cb2 + 1][3],
                         a0, a1, a2, a3, b2_, b3_);
            }
        }
    }
    __syncthreads();   // attention done; smem free for epilogue

    // ---- 1/l per row (register-resident) ----
    lpA += __shfl_xor_sync(0xffffffffu, lpA, 1);
    lpA += __shfl_xor_sync(0xffffffffu, lpA, 2);
    lpB += __shfl_xor_sync(0xffffffffu, lpB, 1);
    lpB += __shfl_xor_sync(0xffffffffu, lpB, 2);

    // ---- Build X = [feats0; feats1; cur] : Xs[384][68] over 64 m ----
    float* Xs = sm;
    {
        float rlA = 1.0f / lpA, rlB = 1.0f / lpB;
        int rA = 16 * warp + (lane >> 2);
        int rB = rA + 8;
        int aSelA = rA >> 6, mmA = rA & 63;
        int aSelB = rB >> 6, mmB = rB & 63;
        #pragma unroll
        for (int cb = 0; cb < 16; cb++) {
            int c = cb * 8 + 2 * (lane & 3);
            Xs[(aSelA * CC + c    ) * 68 + mmA] = O[cb][0] * rlA;
            Xs[(aSelA * CC + c + 1) * 68 + mmA] = O[cb][1] * rlA;
            Xs[(aSelB * CC + c    ) * 68 + mmB] = O[cb][2] * rlB;
            Xs[(aSelB * CC + c + 1) * 68 + mmB] = O[cb][3] * rlB;
        }
    }
    for (int i = tid; i < CC * 64; i += NTHREADS) {
        int c  = i >> 6;
        int mm = i & 63;
        Xs[(2 * CC + c) * 68 + mm] = curb[(size_t)c * HWM + m0 + mm];
    }
    __syncthreads();

    // ---- cls head: y[o][m] = sum_c At[c][o] X[c][m] + dv[o]; leaky; *w2[o] ----
    float y[32];
    float w2o;
    {
        int o    = tid & 127;
        int half = tid >> 7;
        float dv = g_dv[o];
        #pragma unroll
        for (int qq = 0; qq < 32; qq++) y[qq] = dv;

        const float* xb = Xs + half * 32;
        #pragma unroll 2
        for (int c = 0; c < 3 * CC; c++) {
            float a = g_At[c * CC + o];
            const float4* xp = (const float4*)(xb + c * 68);
            #pragma unroll
            for (int v = 0; v < 8; v++) {
                float4 x = xp[v];
                y[4 * v + 0] += a * x.x;
                y[4 * v + 1] += a * x.y;
                y[4 * v + 2] += a * x.z;
                y[4 * v + 3] += a * x.w;
            }
        }
        w2o = w2[o];
    }
    __syncthreads();

    float* Ys = sm;    // [128][66]
    {
        int o    = tid & 127;
        int half = tid >> 7;
        #pragma unroll
        for (int qq = 0; qq < 32; qq++) {
            float v = y[qq];
            v = (v > 0.0f) ? v : 0.01f * v;
            Ys[o * 66 + half * 32 + qq] = w2o * v;
        }
    }
    __syncthreads();

    if (tid < 64) {
        float ssum = b2[0];
        #pragma unroll 4
        for (int o = 0; o < CC; o++) ssum += Ys[o * 66 + tid];
        out[(size_t)b * HWM + m0 + tid] = ssum;
    }
}

extern "C" void kernel_launch(void* const* d_in, const int* in_sizes, int n_in,
                              void* d_out, int out_size)
{
    const float* ref_feat = (const float*)d_in[0];
    const float* cur_feat = (const float*)d_in[1];
    const float* w1       = (const float*)d_in[2];
    const float* b1       = (const float*)d_in[3];
    const float* gamma    = (const float*)d_in[4];
    const float* beta     = (const float*)d_in[5];
    const float* rmean    = (const float*)d_in[6];
    const float* rvar     = (const float*)d_in[7];
    const float* w2       = (const float*)d_in[8];
    const float* b2       = (const float*)d_in[9];
    float* out            = (float*)d_out;

    prep_kernel<<<(3 * CC * CC + 255) / 256, 256>>>(w1, b1, gamma, beta, rmean, rvar);
    conv_kernel<<<(BB * CC * HWM / 4) / 256, 256>>>(cur_feat);
    dim3 tgrid(HWM / 32, CC / 32, BB);
    transpose_kernel<<<tgrid, dim3(32, 8)>>>(cur_feat);

    const int smem_bytes = SMEM_FLOATS * 4;  // 137216
    cudaFuncSetAttribute(fused_attn_rp,
                         cudaFuncAttributeMaxDynamicSharedMemorySize, smem_bytes);

    dim3 grid(HWM / 64, BB);
    fused_attn_rp<<<grid, NTHREADS, smem_bytes>>>(ref_feat, cur_feat, w2, b2, out);
}